// round 13
// baseline (speedup 1.0000x reference)
#include <cuda_runtime.h>
#include <cuda_bf16.h>

#define IMG_H 1080
#define IMG_W 1920
#define THR 20.0f

// Legacy run9 (border path only).
static __device__ __forceinline__ unsigned run9w(unsigned m16) {
    unsigned d = m16 * 0x10001u;
    unsigned r = d & __umulhi(d, 0x80000000u);
    r &= __umulhi(r, 0x40000000u);
    r &= __umulhi(r, 0x10000000u);
    r &= __umulhi(d, 0x01000000u);
    return r;
}

// Merged detection from 16 circle samples c[] and center ctr.
// Packed f32x2 math: d-pair = c-pair + (-ctr,-ctr)  (two exact rounded FADDs),
// s-pair = fma(d,d,-400) (sign exact: |d|<20). Then 32 funnel-shift sign
// gathers + the single run-9 same-sign cascade (verified R11/R12):
//   B = W & ~(G ^ G<<1); det = W_i & B_{i+1..i+8}, circular via *0x10001.
static __device__ __forceinline__ float detect16c(const float* c, float ctr,
                                                  unsigned long long m400_2) {
    float nctr = -ctr;
    unsigned long long nctr2;
    asm("mov.b64 %0, {%1, %2};" : "=l"(nctr2) : "f"(nctr), "f"(nctr));

    unsigned g = 0u, ns = 0u;
#pragma unroll
    for (int i = 14; i >= 0; i -= 2) {
        unsigned long long c2, d2, s2;
        asm("mov.b64 %0, {%1, %2};" : "=l"(c2) : "f"(c[i]), "f"(c[i + 1]));
        asm("add.rn.f32x2 %0, %1, %2;" : "=l"(d2) : "l"(c2), "l"(nctr2));
        asm("fma.rn.f32x2 %0, %1, %2, %3;" : "=l"(s2) : "l"(d2), "l"(d2), "l"(m400_2));
        unsigned dlo, dhi, slo, shi;
        asm("mov.b64 {%0, %1}, %2;" : "=r"(dlo), "=r"(dhi) : "l"(d2));
        asm("mov.b64 {%0, %1}, %2;" : "=r"(slo), "=r"(shi) : "l"(s2));
        // insert bit i+1 then bit i (mask accumulates left; first-in = MSB)
        g  = __funnelshift_l(dhi, g, 1);
        g  = __funnelshift_l(dlo, g, 1);
        ns = __funnelshift_l(shi, ns, 1);
        ns = __funnelshift_l(slo, ns, 1);
    }
    unsigned w  = ~ns & 0xFFFFu;                    // strong bits
    unsigned W  = w * 0x10001u;                     // circular double copy
    unsigned G  = g * 0x10001u;
    unsigned chg = G ^ (G * 2u);                    // bit i = g_i ^ g_{i-1}
    unsigned B  = W & ~chg;                         // strong & same sign as prev
    unsigned b2 = B  & __umulhi(B,  0x80000000u);   // runs >= 2
    unsigned b4 = b2 & __umulhi(b2, 0x40000000u);   // runs >= 4
    unsigned b8 = b4 & __umulhi(b4, 0x10000000u);   // runs >= 8
    unsigned det = W & __umulhi(b8, 0x80000000u);   // W_i & b8_{i+1}
    return __uint_as_float(min(det, 1u) * 0x3F800000u);
}

__global__ __launch_bounds__(96)
void fast_score_kernel(const float* __restrict__ img, float* __restrict__ out, int N)
{
    const int DY[16] = { 0, 1, 2, 3, 3, 3, 2, 1, 0, -1, -2, -3, -3, -3, -2, -1};
    const int DX[16] = {-3, -3, -2, -1, 0, 1, 2, 3, 3, 3, 2, 1, 0, -1, -2, -3};

    int x0 = (blockIdx.x * blockDim.x + threadIdx.x) * 4;
    int y0 = blockIdx.y * 2;            // this thread handles rows y0 and y0+1
    int n  = blockIdx.z;

    const float* im = img + (size_t)n * IMG_H * IMG_W;
    float* op0 = out + ((size_t)n * IMG_H + y0) * IMG_W + x0;
    float* op1 = op0 + IMG_W;

    // (-400, -400) pair, built once.
    unsigned long long m400_2;
    { float m = -400.0f; asm("mov.b64 %0, {%1, %2};" : "=l"(m400_2) : "f"(m), "f"(m)); }

    bool interior = (y0 >= 4) & (y0 <= IMG_H - 6) & (x0 >= 4) & (x0 <= IMG_W - 8);

    if (interior) {
        // Union tile for both center rows (all loads front-batched):
        // T0: y0-3 [x0-1..x0+4](6)   T1: y0-2 [x0-2..x0+5](8)
        // T2: y0-1 [x0-4..x0+7](12)  T3: y0   [x0-4..x0+7](12)
        // T4: y0+1 [x0-4..x0+7](12)  T5: y0+2 [x0-4..x0+7](12)
        // T6: y0+3 [x0-2..x0+5](8)   T7: y0+4 [x0-1..x0+4](6)
        float T0[6], T1[8], T2[12], T3[12], T4[12], T5[12], T6[8], T7[6];
        {
            const float* p;
            p = im + (size_t)(y0 - 3) * IMG_W + x0;
            T0[0] = p[-1];
            { float4 v = *(const float4*)p; T0[1]=v.x; T0[2]=v.y; T0[3]=v.z; T0[4]=v.w; }
            T0[5] = p[4];
            p = im + (size_t)(y0 - 2) * IMG_W + x0;
            { float2 v = *(const float2*)(p - 2); T1[0]=v.x; T1[1]=v.y; }
            { float4 v = *(const float4*)p;       T1[2]=v.x; T1[3]=v.y; T1[4]=v.z; T1[5]=v.w; }
            { float2 v = *(const float2*)(p + 4); T1[6]=v.x; T1[7]=v.y; }
            p = im + (size_t)(y0 - 1) * IMG_W + (x0 - 4);
            { float4 a=*(const float4*)p, b=*(const float4*)(p+4), c=*(const float4*)(p+8);
              T2[0]=a.x;T2[1]=a.y;T2[2]=a.z;T2[3]=a.w;T2[4]=b.x;T2[5]=b.y;T2[6]=b.z;T2[7]=b.w;
              T2[8]=c.x;T2[9]=c.y;T2[10]=c.z;T2[11]=c.w; }
            p = im + (size_t)(y0) * IMG_W + (x0 - 4);
            { float4 a=*(const float4*)p, b=*(const float4*)(p+4), c=*(const float4*)(p+8);
              T3[0]=a.x;T3[1]=a.y;T3[2]=a.z;T3[3]=a.w;T3[4]=b.x;T3[5]=b.y;T3[6]=b.z;T3[7]=b.w;
              T3[8]=c.x;T3[9]=c.y;T3[10]=c.z;T3[11]=c.w; }
            p = im + (size_t)(y0 + 1) * IMG_W + (x0 - 4);
            { float4 a=*(const float4*)p, b=*(const float4*)(p+4), c=*(const float4*)(p+8);
              T4[0]=a.x;T4[1]=a.y;T4[2]=a.z;T4[3]=a.w;T4[4]=b.x;T4[5]=b.y;T4[6]=b.z;T4[7]=b.w;
              T4[8]=c.x;T4[9]=c.y;T4[10]=c.z;T4[11]=c.w; }
            p = im + (size_t)(y0 + 2) * IMG_W + (x0 - 4);
            { float4 a=*(const float4*)p, b=*(const float4*)(p+4), c=*(const float4*)(p+8);
              T5[0]=a.x;T5[1]=a.y;T5[2]=a.z;T5[3]=a.w;T5[4]=b.x;T5[5]=b.y;T5[6]=b.z;T5[7]=b.w;
              T5[8]=c.x;T5[9]=c.y;T5[10]=c.z;T5[11]=c.w; }
            p = im + (size_t)(y0 + 3) * IMG_W + x0;
            { float2 v = *(const float2*)(p - 2); T6[0]=v.x; T6[1]=v.y; }
            { float4 v = *(const float4*)p;       T6[2]=v.x; T6[3]=v.y; T6[4]=v.z; T6[5]=v.w; }
            { float2 v = *(const float2*)(p + 4); T6[6]=v.x; T6[7]=v.y; }
            p = im + (size_t)(y0 + 4) * IMG_W + x0;
            T7[0] = p[-1];
            { float4 v = *(const float4*)p; T7[1]=v.x; T7[2]=v.y; T7[3]=v.z; T7[4]=v.w; }
            T7[5] = p[4];
        }

        float4 res0, res1;
        float* r0p = (float*)&res0;
        float* r1p = (float*)&res1;
#pragma unroll
        for (int p = 0; p < 4; p++) {
            float c[16];
            // ---- center row y0 (roles: R0..R6 = T0..T6) ----
            {
                float ctr = T3[p + 4];
                c[0]  = T3[p + 1];   // (0,-3)
                c[1]  = T4[p + 1];   // (1,-3)
                c[2]  = T5[p + 2];   // (2,-2)  T5 base x0-4
                c[3]  = T6[p + 1];   // (3,-1)  T6 base x0-2
                c[4]  = T6[p + 2];   // (3, 0)
                c[5]  = T6[p + 3];   // (3, 1)
                c[6]  = T5[p + 6];   // (2, 2)
                c[7]  = T4[p + 7];   // (1, 3)
                c[8]  = T3[p + 7];   // (0, 3)
                c[9]  = T2[p + 7];   // (-1,3)
                c[10] = T1[p + 4];   // (-2,2)
                c[11] = T0[p + 2];   // (-3,1)
                c[12] = T0[p + 1];   // (-3,0)
                c[13] = T0[p + 0];   // (-3,-1)
                c[14] = T1[p + 0];   // (-2,-2)
                c[15] = T2[p + 1];   // (-1,-3)
                r0p[p] = detect16c(c, ctr, m400_2);
            }
            // ---- center row y0+1 (roles: R0..R6 = T1..T7) ----
            {
                float ctr = T4[p + 4];
                c[0]  = T4[p + 1];   // (0,-3)
                c[1]  = T5[p + 1];   // (1,-3)  T5 base x0-4
                c[2]  = T6[p + 0];   // (2,-2)  T6 base x0-2
                c[3]  = T7[p + 0];   // (3,-1)  T7 base x0-1
                c[4]  = T7[p + 1];   // (3, 0)
                c[5]  = T7[p + 2];   // (3, 1)
                c[6]  = T6[p + 4];   // (2, 2)
                c[7]  = T5[p + 7];   // (1, 3)
                c[8]  = T4[p + 7];   // (0, 3)
                c[9]  = T3[p + 7];   // (-1,3)
                c[10] = T2[p + 6];   // (-2,2)  T2 base x0-4
                c[11] = T1[p + 3];   // (-3,1)  T1 base x0-2
                c[12] = T1[p + 2];   // (-3,0)
                c[13] = T1[p + 1];   // (-3,-1)
                c[14] = T2[p + 2];   // (-2,-2)
                c[15] = T3[p + 1];   // (-1,-3)
                r1p[p] = detect16c(c, ctr, m400_2);
            }
        }
        *(float4*)op0 = res0;
        *(float4*)op1 = res1;
    } else {
        // Border path: scalar loads with replicate-clamp (rare).
#pragma unroll
        for (int rr = 0; rr < 2; rr++) {
            int y = y0 + rr;
            float* op = (rr == 0) ? op0 : op1;
#pragma unroll
            for (int p = 0; p < 4; p++) {
                int x = x0 + p;
                float center = __ldg(im + (size_t)y * IMG_W + x);
                unsigned dark = 0u, bright = 0u;
#pragma unroll
                for (int i = 0; i < 16; i++) {
                    int yy = min(max(y + DY[i], 0), IMG_H - 1);
                    int xx = min(max(x + DX[i], 0), IMG_W - 1);
                    float diff = __ldg(im + (size_t)yy * IMG_W + xx) - center;
                    if (diff >=  THR) dark   |= (1u << i);
                    if (diff <= -THR) bright |= (1u << i);
                }
                unsigned det = run9w(dark) | run9w(bright);
                op[p] = __uint_as_float(min(det, 1u) * 0x3F800000u);
            }
        }
    }
}

extern "C" void kernel_launch(void* const* d_in, const int* in_sizes, int n_in,
                              void* d_out, int out_size)
{
    const float* img = (const float*)d_in[0];
    float* out = (float*)d_out;
    int N = in_sizes[0] / (IMG_H * IMG_W);

    dim3 block(96, 1, 1);
    // x: 1920/4 px-per-thread = 480 threads -> 5 blocks of 96
    // y: two rows per thread -> 540
    dim3 grid(IMG_W / 4 / 96, IMG_H / 2, N);
    fast_score_kernel<<<grid, block>>>(img, out, N);
}

// round 14
// speedup vs baseline: 1.0132x; 1.0132x over previous
#include <cuda_runtime.h>
#include <cuda_bf16.h>

#define IMG_H 1080
#define IMG_W 1920
#define THR 20.0f

#define NBLOCKS 1184     // 148 SMs x 8 resident blocks
#define TILES_X 5        // 5 x 96 threads x 4 px = 1920
#define TILES_Y 540      // 1080 / 2 rows per tile

// Legacy run9 (border path only).
static __device__ __forceinline__ unsigned run9w(unsigned m16) {
    unsigned d = m16 * 0x10001u;
    unsigned r = d & __umulhi(d, 0x80000000u);
    r &= __umulhi(r, 0x40000000u);
    r &= __umulhi(r, 0x10000000u);
    r &= __umulhi(d, 0x01000000u);
    return r;
}

// Merged detection: 16 diffs -> 1.0f/0.0f (R12 version, verified).
// w = strong (|d|>=20), g = sign(d). Run-9 of strong same-sign at start i
// <=> W_i & B_{i+1..i+8}, B = W & ~(G ^ G<<1), circular via *0x10001.
static __device__ __forceinline__ float detect16(const float* d) {
    unsigned g = 0u, ns = 0u;
#pragma unroll
    for (int i = 15; i >= 0; i--) {
        float s = __fmaf_rn(d[i], d[i], -400.0f);           // sign: |d|<20 (exact;
        g  = __funnelshift_l(__float_as_uint(d[i]), g, 1);  //  |d|==20 -> strong)
        ns = __funnelshift_l(__float_as_uint(s),    ns, 1);
    }
    unsigned w  = ~ns & 0xFFFFu;
    unsigned W  = w * 0x10001u;
    unsigned G  = g * 0x10001u;
    unsigned chg = G ^ (G * 2u);
    unsigned B  = W & ~chg;
    unsigned b2 = B  & __umulhi(B,  0x80000000u);
    unsigned b4 = b2 & __umulhi(b2, 0x40000000u);
    unsigned b8 = b4 & __umulhi(b4, 0x10000000u);
    unsigned det = W & __umulhi(b8, 0x80000000u);
    return __uint_as_float(min(det, 1u) * 0x3F800000u);
}

__global__ __launch_bounds__(96)
void fast_score_kernel(const float* __restrict__ img, float* __restrict__ out,
                       int total_tiles)
{
    const int DY[16] = { 0, 1, 2, 3, 3, 3, 2, 1, 0, -1, -2, -3, -3, -3, -2, -1};
    const int DX[16] = {-3, -3, -2, -1, 0, 1, 2, 3, 3, 3, 2, 1, 0, -1, -2, -3};

    int tid = threadIdx.x;

    // Persistent grid-stride over tiles: removes wave-transition overhead
    // (10800 short blocks -> 1184 resident blocks x ~9 iterations).
    for (int t = blockIdx.x; t < total_tiles; t += gridDim.x) {
        int n   = t / (TILES_X * TILES_Y);
        int rem = t - n * (TILES_X * TILES_Y);
        int by  = rem / TILES_X;
        int bx  = rem - by * TILES_X;

        int x0 = (bx * 96 + tid) * 4;
        int y0 = by * 2;

        const float* im = img + (size_t)n * IMG_H * IMG_W;
        float* op0 = out + ((size_t)n * IMG_H + y0) * IMG_W + x0;
        float* op1 = op0 + IMG_W;

        bool interior = (y0 >= 4) & (y0 <= IMG_H - 6) & (x0 >= 4) & (x0 <= IMG_W - 8);

        if (interior) {
            // Union tile, all loads front-batched (R12 layout):
            float T0[6], T1[8], T2[12], T3[12], T4[12], T5[12], T6[8], T7[6];
            {
                const float* p;
                p = im + (size_t)(y0 - 3) * IMG_W + x0;
                T0[0] = p[-1];
                { float4 v = *(const float4*)p; T0[1]=v.x; T0[2]=v.y; T0[3]=v.z; T0[4]=v.w; }
                T0[5] = p[4];
                p = im + (size_t)(y0 - 2) * IMG_W + x0;
                { float2 v = *(const float2*)(p - 2); T1[0]=v.x; T1[1]=v.y; }
                { float4 v = *(const float4*)p;       T1[2]=v.x; T1[3]=v.y; T1[4]=v.z; T1[5]=v.w; }
                { float2 v = *(const float2*)(p + 4); T1[6]=v.x; T1[7]=v.y; }
                p = im + (size_t)(y0 - 1) * IMG_W + (x0 - 4);
                { float4 a=*(const float4*)p, b=*(const float4*)(p+4), c=*(const float4*)(p+8);
                  T2[0]=a.x;T2[1]=a.y;T2[2]=a.z;T2[3]=a.w;T2[4]=b.x;T2[5]=b.y;T2[6]=b.z;T2[7]=b.w;
                  T2[8]=c.x;T2[9]=c.y;T2[10]=c.z;T2[11]=c.w; }
                p = im + (size_t)(y0) * IMG_W + (x0 - 4);
                { float4 a=*(const float4*)p, b=*(const float4*)(p+4), c=*(const float4*)(p+8);
                  T3[0]=a.x;T3[1]=a.y;T3[2]=a.z;T3[3]=a.w;T3[4]=b.x;T3[5]=b.y;T3[6]=b.z;T3[7]=b.w;
                  T3[8]=c.x;T3[9]=c.y;T3[10]=c.z;T3[11]=c.w; }
                p = im + (size_t)(y0 + 1) * IMG_W + (x0 - 4);
                { float4 a=*(const float4*)p, b=*(const float4*)(p+4), c=*(const float4*)(p+8);
                  T4[0]=a.x;T4[1]=a.y;T4[2]=a.z;T4[3]=a.w;T4[4]=b.x;T4[5]=b.y;T4[6]=b.z;T4[7]=b.w;
                  T4[8]=c.x;T4[9]=c.y;T4[10]=c.z;T4[11]=c.w; }
                p = im + (size_t)(y0 + 2) * IMG_W + (x0 - 4);
                { float4 a=*(const float4*)p, b=*(const float4*)(p+4), c=*(const float4*)(p+8);
                  T5[0]=a.x;T5[1]=a.y;T5[2]=a.z;T5[3]=a.w;T5[4]=b.x;T5[5]=b.y;T5[6]=b.z;T5[7]=b.w;
                  T5[8]=c.x;T5[9]=c.y;T5[10]=c.z;T5[11]=c.w; }
                p = im + (size_t)(y0 + 3) * IMG_W + x0;
                { float2 v = *(const float2*)(p - 2); T6[0]=v.x; T6[1]=v.y; }
                { float4 v = *(const float4*)p;       T6[2]=v.x; T6[3]=v.y; T6[4]=v.z; T6[5]=v.w; }
                { float2 v = *(const float2*)(p + 4); T6[6]=v.x; T6[7]=v.y; }
                p = im + (size_t)(y0 + 4) * IMG_W + x0;
                T7[0] = p[-1];
                { float4 v = *(const float4*)p; T7[1]=v.x; T7[2]=v.y; T7[3]=v.z; T7[4]=v.w; }
                T7[5] = p[4];
            }

            float4 res0, res1;
            float* r0p = (float*)&res0;
            float* r1p = (float*)&res1;
#pragma unroll
            for (int p = 0; p < 4; p++) {
                float d[16];
                // ---- center row y0 ----
                {
                    float ctr = T3[p + 4];
                    d[0]  = T3[p + 1] - ctr;   d[1]  = T4[p + 1] - ctr;
                    d[2]  = T5[p + 2] - ctr;   d[3]  = T6[p + 1] - ctr;
                    d[4]  = T6[p + 2] - ctr;   d[5]  = T6[p + 3] - ctr;
                    d[6]  = T5[p + 6] - ctr;   d[7]  = T4[p + 7] - ctr;
                    d[8]  = T3[p + 7] - ctr;   d[9]  = T2[p + 7] - ctr;
                    d[10] = T1[p + 4] - ctr;   d[11] = T0[p + 2] - ctr;
                    d[12] = T0[p + 1] - ctr;   d[13] = T0[p + 0] - ctr;
                    d[14] = T1[p + 0] - ctr;   d[15] = T2[p + 1] - ctr;
                    r0p[p] = detect16(d);
                }
                // ---- center row y0+1 ----
                {
                    float ctr = T4[p + 4];
                    d[0]  = T4[p + 1] - ctr;   d[1]  = T5[p + 1] - ctr;
                    d[2]  = T6[p + 0] - ctr;   d[3]  = T7[p + 0] - ctr;
                    d[4]  = T7[p + 1] - ctr;   d[5]  = T7[p + 2] - ctr;
                    d[6]  = T6[p + 4] - ctr;   d[7]  = T5[p + 7] - ctr;
                    d[8]  = T4[p + 7] - ctr;   d[9]  = T3[p + 7] - ctr;
                    d[10] = T2[p + 6] - ctr;   d[11] = T1[p + 3] - ctr;
                    d[12] = T1[p + 2] - ctr;   d[13] = T1[p + 1] - ctr;
                    d[14] = T2[p + 2] - ctr;   d[15] = T3[p + 1] - ctr;
                    r1p[p] = detect16(d);
                }
            }
            *(float4*)op0 = res0;
            *(float4*)op1 = res1;
        } else {
            // Border path: scalar loads with replicate-clamp (rare).
#pragma unroll
            for (int rr = 0; rr < 2; rr++) {
                int y = y0 + rr;
                float* op = (rr == 0) ? op0 : op1;
#pragma unroll
                for (int p = 0; p < 4; p++) {
                    int x = x0 + p;
                    float center = __ldg(im + (size_t)y * IMG_W + x);
                    unsigned dark = 0u, bright = 0u;
#pragma unroll
                    for (int i = 0; i < 16; i++) {
                        int yy = min(max(y + DY[i], 0), IMG_H - 1);
                        int xx = min(max(x + DX[i], 0), IMG_W - 1);
                        float diff = __ldg(im + (size_t)yy * IMG_W + xx) - center;
                        if (diff >=  THR) dark   |= (1u << i);
                        if (diff <= -THR) bright |= (1u << i);
                    }
                    unsigned det = run9w(dark) | run9w(bright);
                    op[p] = __uint_as_float(min(det, 1u) * 0x3F800000u);
                }
            }
        }
    }
}

extern "C" void kernel_launch(void* const* d_in, const int* in_sizes, int n_in,
                              void* d_out, int out_size)
{
    const float* img = (const float*)d_in[0];
    float* out = (float*)d_out;
    int N = in_sizes[0] / (IMG_H * IMG_W);
    int total_tiles = TILES_X * TILES_Y * N;     // 10800 for N=4

    dim3 block(96, 1, 1);
    dim3 grid(NBLOCKS, 1, 1);
    fast_score_kernel<<<grid, block>>>(img, out, total_tiles);
}

// round 15
// speedup vs baseline: 1.1301x; 1.1154x over previous
#include <cuda_runtime.h>
#include <cuda_bf16.h>

#define IMG_H 1080
#define IMG_W 1920
#define NB    1184          // persistent blocks (148 SMs x 8)
#define TX    5             // 5 x (96 thr x 4 px) = 1920
#define TY    540           // 1080 / 2 rows per tile
#define TPI   (TX * TY)     // tiles per image
#define SROW  396           // staged floats per row: 4 halo + 384 + 8 halo

static __device__ __forceinline__ unsigned smem_u32(const void* p) {
    unsigned a;
    asm("{ .reg .u64 t; cvta.to.shared.u64 t, %1; cvt.u32.u64 %0, t; }" : "=r"(a) : "l"(p));
    return a;
}

// Merged detection: 16 diffs -> 1.0f/0.0f (R12 version, verified exact).
// w = strong (|d|>=20, via sign of fma(d,d,-400)), g = sign(d). Run-9 of
// strong same-sign at start i <=> W_i & B_{i+1..i+8}, B = W & ~(G ^ G<<1),
// circular via *0x10001; high windows self-clear, det != 0 iff detection.
static __device__ __forceinline__ float detect16(const float* d) {
    unsigned g = 0u, ns = 0u;
#pragma unroll
    for (int i = 15; i >= 0; i--) {
        float s = __fmaf_rn(d[i], d[i], -400.0f);
        g  = __funnelshift_l(__float_as_uint(d[i]), g, 1);
        ns = __funnelshift_l(__float_as_uint(s),    ns, 1);
    }
    unsigned w  = ~ns & 0xFFFFu;
    unsigned W  = w * 0x10001u;
    unsigned G  = g * 0x10001u;
    unsigned chg = G ^ (G * 2u);
    unsigned B  = W & ~chg;
    unsigned b2 = B  & __umulhi(B,  0x80000000u);
    unsigned b4 = b2 & __umulhi(b2, 0x40000000u);
    unsigned b8 = b4 & __umulhi(b4, 0x10000000u);
    unsigned det = W & __umulhi(b8, 0x80000000u);
    return __uint_as_float(min(det, 1u) * 0x3F800000u);
}

// Stage one tile's 8 rows (with replicate row/col clamp) into smem buffer sb.
// 96 interior float4 chunks per row (1 per thread) + 12 halo scalars per row
// (96 total = 1 per thread). Every staged byte written exactly once.
static __device__ __forceinline__ void stage_tile(const float* __restrict__ img, int t,
                                                  unsigned sb, int tid, int hr, int hj) {
    int n  = t / TPI;  int rm = t - n * TPI;
    int by = rm / TX;  int bx = rm - by * TX;
    int y0 = by * 2;   int X0 = bx * 384;
    const float* im = img + (size_t)n * (IMG_H * IMG_W);
#pragma unroll
    for (int r = 0; r < 8; r++) {
        int gy = min(max(y0 - 3 + r, 0), IMG_H - 1);
        const float* src = im + (size_t)gy * IMG_W + (X0 + tid * 4);
        unsigned dst = sb + (unsigned)(r * SROW + 4 + tid * 4) * 4u;
        asm volatile("cp.async.ca.shared.global [%0], [%1], 16;" :: "r"(dst), "l"(src));
    }
    {
        int gy = min(max(y0 - 3 + hr, 0), IMG_H - 1);
        int gx = (hj < 4) ? max(X0 - 4 + hj, 0) : min(X0 + 380 + hj, IMG_W - 1);
        int si = (hj < 4) ? hj : (384 + hj);
        const float* src = im + (size_t)gy * IMG_W + gx;
        unsigned dst = sb + (unsigned)(hr * SROW + si) * 4u;
        asm volatile("cp.async.ca.shared.global [%0], [%1], 4;" :: "r"(dst), "l"(src));
    }
}

__global__ __launch_bounds__(96)
void fast_score_kernel(const float* __restrict__ img, float* __restrict__ out,
                       int total_tiles)
{
    __shared__ float S[2][8][SROW];

    int tid = threadIdx.x;
    int hr  = tid / 12;          // halo row (96 = 8 rows x 12 halo cols)
    int hj  = tid - hr * 12;     // halo col id 0..11

    // Prologue: stage first tile into buffer 0.
    stage_tile(img, blockIdx.x, smem_u32(&S[0][0][0]), tid, hr, hj);
    asm volatile("cp.async.commit_group;");

    int par = 0;
    for (int t = blockIdx.x; t < total_tiles; t += NB) {
        int tn = t + NB;
        __syncthreads();                       // readers of buf[par^1] done
        if (tn < total_tiles) {
            stage_tile(img, tn, smem_u32(&S[par ^ 1][0][0]), tid, hr, hj);
            asm volatile("cp.async.commit_group;");
            asm volatile("cp.async.wait_group 1;");   // current tile complete
        } else {
            asm volatile("cp.async.wait_group 0;");
        }
        __syncthreads();                       // staged data visible to all

        // ---- compute current tile from S[par] (uniform: no border branch) ----
        {
            int n  = t / TPI;  int rm = t - n * TPI;
            int by = rm / TX;  int bx = rm - by * TX;
            int y0 = by * 2;   int X0 = bx * 384;
            const float (*Sr)[SROW] = S[par];
            int s = tid * 4;                   // staged idx of (x0 - 4)

            // Register tile (R12 layout; bases: T0 x0-1, T1 x0-2, T2..T5 x0-4,
            // T6 x0-2, T7 x0-1):
            float T0[6], T1[8], T2[12], T3[12], T4[12], T5[12], T6[8], T7[6];
            T0[0] = Sr[0][s + 3];
            { float4 v = *(const float4*)&Sr[0][s + 4]; T0[1]=v.x; T0[2]=v.y; T0[3]=v.z; T0[4]=v.w; }
            T0[5] = Sr[0][s + 8];
            { float2 v = *(const float2*)&Sr[1][s + 2]; T1[0]=v.x; T1[1]=v.y; }
            { float4 v = *(const float4*)&Sr[1][s + 4]; T1[2]=v.x; T1[3]=v.y; T1[4]=v.z; T1[5]=v.w; }
            { float2 v = *(const float2*)&Sr[1][s + 8]; T1[6]=v.x; T1[7]=v.y; }
#pragma unroll
            for (int rr = 0; rr < 4; rr++) {
                float* T = (rr == 0) ? T2 : (rr == 1) ? T3 : (rr == 2) ? T4 : T5;
                { float4 a = *(const float4*)&Sr[2 + rr][s];
                  float4 b = *(const float4*)&Sr[2 + rr][s + 4];
                  float4 c = *(const float4*)&Sr[2 + rr][s + 8];
                  T[0]=a.x;T[1]=a.y;T[2]=a.z;T[3]=a.w;T[4]=b.x;T[5]=b.y;T[6]=b.z;T[7]=b.w;
                  T[8]=c.x;T[9]=c.y;T[10]=c.z;T[11]=c.w; }
            }
            { float2 v = *(const float2*)&Sr[6][s + 2]; T6[0]=v.x; T6[1]=v.y; }
            { float4 v = *(const float4*)&Sr[6][s + 4]; T6[2]=v.x; T6[3]=v.y; T6[4]=v.z; T6[5]=v.w; }
            { float2 v = *(const float2*)&Sr[6][s + 8]; T6[6]=v.x; T6[7]=v.y; }
            T7[0] = Sr[7][s + 3];
            { float4 v = *(const float4*)&Sr[7][s + 4]; T7[1]=v.x; T7[2]=v.y; T7[3]=v.z; T7[4]=v.w; }
            T7[5] = Sr[7][s + 8];

            float4 res0, res1;
            float* r0p = (float*)&res0;
            float* r1p = (float*)&res1;
#pragma unroll
            for (int p = 0; p < 4; p++) {
                float d[16];
                // ---- center row y0 (roles R0..R6 = T0..T6) ----
                {
                    float ctr = T3[p + 4];
                    d[0]  = T3[p + 1] - ctr;   d[1]  = T4[p + 1] - ctr;
                    d[2]  = T5[p + 2] - ctr;   d[3]  = T6[p + 1] - ctr;
                    d[4]  = T6[p + 2] - ctr;   d[5]  = T6[p + 3] - ctr;
                    d[6]  = T5[p + 6] - ctr;   d[7]  = T4[p + 7] - ctr;
                    d[8]  = T3[p + 7] - ctr;   d[9]  = T2[p + 7] - ctr;
                    d[10] = T1[p + 4] - ctr;   d[11] = T0[p + 2] - ctr;
                    d[12] = T0[p + 1] - ctr;   d[13] = T0[p + 0] - ctr;
                    d[14] = T1[p + 0] - ctr;   d[15] = T2[p + 1] - ctr;
                    r0p[p] = detect16(d);
                }
                // ---- center row y0+1 (roles R0..R6 = T1..T7) ----
                {
                    float ctr = T4[p + 4];
                    d[0]  = T4[p + 1] - ctr;   d[1]  = T5[p + 1] - ctr;
                    d[2]  = T6[p + 0] - ctr;   d[3]  = T7[p + 0] - ctr;
                    d[4]  = T7[p + 1] - ctr;   d[5]  = T7[p + 2] - ctr;
                    d[6]  = T6[p + 4] - ctr;   d[7]  = T5[p + 7] - ctr;
                    d[8]  = T4[p + 7] - ctr;   d[9]  = T3[p + 7] - ctr;
                    d[10] = T2[p + 6] - ctr;   d[11] = T1[p + 3] - ctr;
                    d[12] = T1[p + 2] - ctr;   d[13] = T1[p + 1] - ctr;
                    d[14] = T2[p + 2] - ctr;   d[15] = T3[p + 1] - ctr;
                    r1p[p] = detect16(d);
                }
            }
            float* op0 = out + ((size_t)n * IMG_H + y0) * IMG_W + X0 + tid * 4;
            *(float4*)op0 = res0;
            *(float4*)(op0 + IMG_W) = res1;
        }
        par ^= 1;
    }
}

extern "C" void kernel_launch(void* const* d_in, const int* in_sizes, int n_in,
                              void* d_out, int out_size)
{
    const float* img = (const float*)d_in[0];
    float* out = (float*)d_out;
    int N = in_sizes[0] / (IMG_H * IMG_W);
    int total_tiles = TPI * N;     // 10800 for N=4

    dim3 block(96, 1, 1);
    dim3 grid(NB, 1, 1);
    fast_score_kernel<<<grid, block>>>(img, out, total_tiles);
}

// round 16
// speedup vs baseline: 1.1803x; 1.0444x over previous
#include <cuda_runtime.h>
#include <cuda_bf16.h>

#define IMG_H 1080
#define IMG_W 1920
#define NB    1184          // persistent blocks (148 SMs x 8)
#define TX    5             // 5 x (96 thr x 4 px) = 1920
#define TY    540           // 1080 / 2 rows per tile
#define TPI   (TX * TY)     // tiles per image
#define SROW  396           // staged floats per row: 4 halo + 384 + 8 halo

static __device__ __forceinline__ unsigned smem_u32(const void* p) {
    unsigned a;
    asm("{ .reg .u64 t; cvta.to.shared.u64 t, %1; cvt.u32.u64 %0, t; }" : "=r"(a) : "l"(p));
    return a;
}

// Merged detection: 16 diffs -> 1.0f/0.0f (R12 version, verified exact).
// w = strong (|d|>=20, via sign of fma(d,d,-400)), g = sign(d). Run-9 of
// strong same-sign at start i <=> W_i & B_{i+1..i+8}, B = W & ~(G ^ G<<1),
// circular via *0x10001; high windows self-clear, det != 0 iff detection.
static __device__ __forceinline__ float detect16(const float* d) {
    unsigned g = 0u, ns = 0u;
#pragma unroll
    for (int i = 15; i >= 0; i--) {
        float s = __fmaf_rn(d[i], d[i], -400.0f);
        g  = __funnelshift_l(__float_as_uint(d[i]), g, 1);
        ns = __funnelshift_l(__float_as_uint(s),    ns, 1);
    }
    unsigned w  = ~ns & 0xFFFFu;
    unsigned W  = w * 0x10001u;
    unsigned G  = g * 0x10001u;
    unsigned chg = G ^ (G * 2u);
    unsigned B  = W & ~chg;
    unsigned b2 = B  & __umulhi(B,  0x80000000u);
    unsigned b4 = b2 & __umulhi(b2, 0x40000000u);
    unsigned b8 = b4 & __umulhi(b4, 0x10000000u);
    unsigned det = W & __umulhi(b8, 0x80000000u);
    return __uint_as_float(min(det, 1u) * 0x3F800000u);
}

// Stage one tile's 8 rows (with replicate row/col clamp) into smem buffer sb.
// 96 interior float4 chunks per row (1 per thread) + 12 halo scalars per row
// (96 total = 1 per thread). Every staged byte written exactly once.
static __device__ __forceinline__ void stage_tile(const float* __restrict__ img, int t,
                                                  unsigned sb, int tid, int hr, int hj) {
    int n  = t / TPI;  int rm = t - n * TPI;
    int by = rm / TX;  int bx = rm - by * TX;
    int y0 = by * 2;   int X0 = bx * 384;
    const float* im = img + (size_t)n * (IMG_H * IMG_W);
#pragma unroll
    for (int r = 0; r < 8; r++) {
        int gy = min(max(y0 - 3 + r, 0), IMG_H - 1);
        const float* src = im + (size_t)gy * IMG_W + (X0 + tid * 4);
        unsigned dst = sb + (unsigned)(r * SROW + 4 + tid * 4) * 4u;
        asm volatile("cp.async.ca.shared.global [%0], [%1], 16;" :: "r"(dst), "l"(src));
    }
    {
        int gy = min(max(y0 - 3 + hr, 0), IMG_H - 1);
        int gx = (hj < 4) ? max(X0 - 4 + hj, 0) : min(X0 + 380 + hj, IMG_W - 1);
        int si = (hj < 4) ? hj : (384 + hj);
        const float* src = im + (size_t)gy * IMG_W + gx;
        unsigned dst = sb + (unsigned)(hr * SROW + si) * 4u;
        asm volatile("cp.async.ca.shared.global [%0], [%1], 4;" :: "r"(dst), "l"(src));
    }
}

__global__ __launch_bounds__(96)
void fast_score_kernel(const float* __restrict__ img, float* __restrict__ out,
                       int total_tiles)
{
    __shared__ float S[2][8][SROW];

    int tid = threadIdx.x;
    int hr  = tid / 12;          // halo row (96 = 8 rows x 12 halo cols)
    int hj  = tid - hr * 12;     // halo col id 0..11

    // Prologue: stage first tile into buffer 0.
    stage_tile(img, blockIdx.x, smem_u32(&S[0][0][0]), tid, hr, hj);
    asm volatile("cp.async.commit_group;");

    int par = 0;
    for (int t = blockIdx.x; t < total_tiles; t += NB) {
        int tn = t + NB;
        __syncthreads();                       // readers of buf[par^1] done
        if (tn < total_tiles) {
            stage_tile(img, tn, smem_u32(&S[par ^ 1][0][0]), tid, hr, hj);
            asm volatile("cp.async.commit_group;");
            asm volatile("cp.async.wait_group 1;");   // current tile complete
        } else {
            asm volatile("cp.async.wait_group 0;");
        }
        __syncthreads();                       // staged data visible to all

        // ---- compute current tile from S[par] (uniform: no border branch) ----
        {
            int n  = t / TPI;  int rm = t - n * TPI;
            int by = rm / TX;  int bx = rm - by * TX;
            int y0 = by * 2;   int X0 = bx * 384;
            const float (*Sr)[SROW] = S[par];
            int s = tid * 4;                   // staged idx of (x0 - 4)

            // Register tile (R12 layout; bases: T0 x0-1, T1 x0-2, T2..T5 x0-4,
            // T6 x0-2, T7 x0-1):
            float T0[6], T1[8], T2[12], T3[12], T4[12], T5[12], T6[8], T7[6];
            T0[0] = Sr[0][s + 3];
            { float4 v = *(const float4*)&Sr[0][s + 4]; T0[1]=v.x; T0[2]=v.y; T0[3]=v.z; T0[4]=v.w; }
            T0[5] = Sr[0][s + 8];
            { float2 v = *(const float2*)&Sr[1][s + 2]; T1[0]=v.x; T1[1]=v.y; }
            { float4 v = *(const float4*)&Sr[1][s + 4]; T1[2]=v.x; T1[3]=v.y; T1[4]=v.z; T1[5]=v.w; }
            { float2 v = *(const float2*)&Sr[1][s + 8]; T1[6]=v.x; T1[7]=v.y; }
#pragma unroll
            for (int rr = 0; rr < 4; rr++) {
                float* T = (rr == 0) ? T2 : (rr == 1) ? T3 : (rr == 2) ? T4 : T5;
                { float4 a = *(const float4*)&Sr[2 + rr][s];
                  float4 b = *(const float4*)&Sr[2 + rr][s + 4];
                  float4 c = *(const float4*)&Sr[2 + rr][s + 8];
                  T[0]=a.x;T[1]=a.y;T[2]=a.z;T[3]=a.w;T[4]=b.x;T[5]=b.y;T[6]=b.z;T[7]=b.w;
                  T[8]=c.x;T[9]=c.y;T[10]=c.z;T[11]=c.w; }
            }
            { float2 v = *(const float2*)&Sr[6][s + 2]; T6[0]=v.x; T6[1]=v.y; }
            { float4 v = *(const float4*)&Sr[6][s + 4]; T6[2]=v.x; T6[3]=v.y; T6[4]=v.z; T6[5]=v.w; }
            { float2 v = *(const float2*)&Sr[6][s + 8]; T6[6]=v.x; T6[7]=v.y; }
            T7[0] = Sr[7][s + 3];
            { float4 v = *(const float4*)&Sr[7][s + 4]; T7[1]=v.x; T7[2]=v.y; T7[3]=v.z; T7[4]=v.w; }
            T7[5] = Sr[7][s + 8];

            float4 res0, res1;
            float* r0p = (float*)&res0;
            float* r1p = (float*)&res1;
#pragma unroll
            for (int p = 0; p < 4; p++) {
                float d[16];
                // ---- center row y0 (roles R0..R6 = T0..T6) ----
                {
                    float ctr = T3[p + 4];
                    d[0]  = T3[p + 1] - ctr;   d[1]  = T4[p + 1] - ctr;
                    d[2]  = T5[p + 2] - ctr;   d[3]  = T6[p + 1] - ctr;
                    d[4]  = T6[p + 2] - ctr;   d[5]  = T6[p + 3] - ctr;
                    d[6]  = T5[p + 6] - ctr;   d[7]  = T4[p + 7] - ctr;
                    d[8]  = T3[p + 7] - ctr;   d[9]  = T2[p + 7] - ctr;
                    d[10] = T1[p + 4] - ctr;   d[11] = T0[p + 2] - ctr;
                    d[12] = T0[p + 1] - ctr;   d[13] = T0[p + 0] - ctr;
                    d[14] = T1[p + 0] - ctr;   d[15] = T2[p + 1] - ctr;
                    r0p[p] = detect16(d);
                }
                // ---- center row y0+1 (roles R0..R6 = T1..T7) ----
                {
                    float ctr = T4[p + 4];
                    d[0]  = T4[p + 1] - ctr;   d[1]  = T5[p + 1] - ctr;
                    d[2]  = T6[p + 0] - ctr;   d[3]  = T7[p + 0] - ctr;
                    d[4]  = T7[p + 1] - ctr;   d[5]  = T7[p + 2] - ctr;
                    d[6]  = T6[p + 4] - ctr;   d[7]  = T5[p + 7] - ctr;
                    d[8]  = T4[p + 7] - ctr;   d[9]  = T3[p + 7] - ctr;
                    d[10] = T2[p + 6] - ctr;   d[11] = T1[p + 3] - ctr;
                    d[12] = T1[p + 2] - ctr;   d[13] = T1[p + 1] - ctr;
                    d[14] = T2[p + 2] - ctr;   d[15] = T3[p + 1] - ctr;
                    r1p[p] = detect16(d);
                }
            }
            float* op0 = out + ((size_t)n * IMG_H + y0) * IMG_W + X0 + tid * 4;
            *(float4*)op0 = res0;
            *(float4*)(op0 + IMG_W) = res1;
        }
        par ^= 1;
    }
}

extern "C" void kernel_launch(void* const* d_in, const int* in_sizes, int n_in,
                              void* d_out, int out_size)
{
    const float* img = (const float*)d_in[0];
    float* out = (float*)d_out;
    int N = in_sizes[0] / (IMG_H * IMG_W);
    int total_tiles = TPI * N;     // 10800 for N=4

    dim3 block(96, 1, 1);
    dim3 grid(NB, 1, 1);
    fast_score_kernel<<<grid, block>>>(img, out, total_tiles);
}

// round 17
// speedup vs baseline: 1.1813x; 1.0009x over previous
#include <cuda_runtime.h>
#include <cuda_bf16.h>

#define IMG_H 1080
#define IMG_W 1920
#define NB    1184          // persistent blocks (148 SMs x 8)
#define WPB   3             // warps per block
#define NWARP (NB * WPB)    // 3552 persistent warps
#define TXW   15            // x-tiles: 15 x (32 lanes x 4 px) = 1920
#define TYW   540           // 1080 / 2 rows per tile
#define TPI   (TXW * TYW)   // warp-tiles per image (8100)
#define SROW  144           // staged floats per row (4 halo + 128 + 8 halo + pad)

// Merged detection: 16 diffs -> 1.0f/0.0f (R12 version, verified exact).
// w = strong (|d|>=20 via sign of fma(d,d,-400)), g = sign(d). Run-9 of
// strong same-sign at start i <=> W_i & B_{i+1..i+8}, B = W & ~(G ^ G<<1),
// circular via *0x10001; high windows self-clear, det != 0 iff detection.
static __device__ __forceinline__ float detect16(const float* d) {
    unsigned g = 0u, ns = 0u;
#pragma unroll
    for (int i = 15; i >= 0; i--) {
        float s = __fmaf_rn(d[i], d[i], -400.0f);
        g  = __funnelshift_l(__float_as_uint(d[i]), g, 1);
        ns = __funnelshift_l(__float_as_uint(s),    ns, 1);
    }
    unsigned w  = ~ns & 0xFFFFu;
    unsigned W  = w * 0x10001u;
    unsigned G  = g * 0x10001u;
    unsigned chg = G ^ (G * 2u);
    unsigned B  = W & ~chg;
    unsigned b2 = B  & __umulhi(B,  0x80000000u);
    unsigned b4 = b2 & __umulhi(b2, 0x40000000u);
    unsigned b8 = b4 & __umulhi(b4, 0x10000000u);
    unsigned det = W & __umulhi(b8, 0x80000000u);
    return __uint_as_float(min(det, 1u) * 0x3F800000u);
}

static __device__ __forceinline__ unsigned smem_u32(const void* p) {
    unsigned a;
    asm("{ .reg .u64 t; cvta.to.shared.u64 t, %1; cvt.u32.u64 %0, t; }" : "=r"(a) : "l"(p));
    return a;
}

// Warp-private staging of one tile: 8 rows x [X0-4, X0+136) with replicate
// row/col clamp. Per lane: 8 interior 16B cp.async (row r, cols X0+4*lane..+3)
// + 3 clamped 4B halo cp.async. Division-free interior addressing.
static __device__ __forceinline__ void stage_tile(const float* __restrict__ img,
                                                  int t, unsigned sb, int lane) {
    int n  = t / TPI;  int rm = t - n * TPI;
    int by = rm / TXW; int bx = rm - by * TXW;
    int y0 = by * 2;   int X0 = bx * 128;
    const float* im = img + (size_t)n * (IMG_H * IMG_W);
#pragma unroll
    for (int r = 0; r < 8; r++) {
        int gy = min(max(y0 - 3 + r, 0), IMG_H - 1);
        const float* src = im + (size_t)gy * IMG_W + (X0 + lane * 4);
        unsigned dst = sb + (unsigned)(r * SROW + 4 + lane * 4) * 4u;
        asm volatile("cp.async.ca.shared.global [%0], [%1], 16;" :: "r"(dst), "l"(src));
    }
#pragma unroll
    for (int m = 0; m < 3; m++) {
        int k  = lane * 3 + m;          // 0..95 = 8 rows x 12 halo cols
        int hr = k / 12;
        int hj = k - hr * 12;
        int gy = min(max(y0 - 3 + hr, 0), IMG_H - 1);
        int gx = (hj < 4) ? max(X0 - 4 + hj, 0) : min(X0 + 124 + hj, IMG_W - 1);
        int si = (hj < 4) ? hj : (128 + hj);
        const float* src = im + (size_t)gy * IMG_W + gx;
        unsigned dst = sb + (unsigned)(hr * SROW + si) * 4u;
        asm volatile("cp.async.ca.shared.global [%0], [%1], 4;" :: "r"(dst), "l"(src));
    }
}

__global__ __launch_bounds__(96)
void fast_score_kernel(const float* __restrict__ img, float* __restrict__ out,
                       int total_tiles)
{
    __shared__ float S[WPB][2][8][SROW];   // warp-private double buffers

    int lane = threadIdx.x & 31;
    int wid  = threadIdx.x >> 5;
    int gw   = blockIdx.x * WPB + wid;     // persistent warp id

    unsigned sb0 = smem_u32(&S[wid][0][0][0]);
    unsigned sb1 = smem_u32(&S[wid][1][0][0]);

    // Prologue: stage first tile into buffer 0.
    stage_tile(img, gw, sb0, lane);
    asm volatile("cp.async.commit_group;");

    int par = 0;
    for (int t = gw; t < total_tiles; t += NWARP) {
        int tn = t + NWARP;
        if (tn < total_tiles) {
            stage_tile(img, tn, par ? sb0 : sb1, lane);
            asm volatile("cp.async.commit_group;");
            asm volatile("cp.async.wait_group 1;");   // current tile done
        } else {
            asm volatile("cp.async.wait_group 0;");
        }
        __syncwarp();                                  // cross-lane visibility

        // ---- compute current tile (uniform path; smem holds clamped halo) ----
        {
            int n  = t / TPI;  int rm = t - n * TPI;
            int by = rm / TXW; int bx = rm - by * TXW;
            int y0 = by * 2;   int X0 = bx * 128;
            const float (*Sr)[SROW] = S[wid][par];
            int s = lane * 4;                          // staged col of (x0 - 4)

            // Register tile (R12 layout):
            float T0[6], T1[8], T2[12], T3[12], T4[12], T5[12], T6[8], T7[6];
            T0[0] = Sr[0][s + 3];
            { float4 v = *(const float4*)&Sr[0][s + 4]; T0[1]=v.x; T0[2]=v.y; T0[3]=v.z; T0[4]=v.w; }
            T0[5] = Sr[0][s + 8];
            { float2 v = *(const float2*)&Sr[1][s + 2]; T1[0]=v.x; T1[1]=v.y; }
            { float4 v = *(const float4*)&Sr[1][s + 4]; T1[2]=v.x; T1[3]=v.y; T1[4]=v.z; T1[5]=v.w; }
            { float2 v = *(const float2*)&Sr[1][s + 8]; T1[6]=v.x; T1[7]=v.y; }
#pragma unroll
            for (int rr = 0; rr < 4; rr++) {
                float* T = (rr == 0) ? T2 : (rr == 1) ? T3 : (rr == 2) ? T4 : T5;
                float4 a = *(const float4*)&Sr[2 + rr][s];
                float4 b = *(const float4*)&Sr[2 + rr][s + 4];
                float4 c = *(const float4*)&Sr[2 + rr][s + 8];
                T[0]=a.x;T[1]=a.y;T[2]=a.z;T[3]=a.w;T[4]=b.x;T[5]=b.y;T[6]=b.z;T[7]=b.w;
                T[8]=c.x;T[9]=c.y;T[10]=c.z;T[11]=c.w;
            }
            { float2 v = *(const float2*)&Sr[6][s + 2]; T6[0]=v.x; T6[1]=v.y; }
            { float4 v = *(const float4*)&Sr[6][s + 4]; T6[2]=v.x; T6[3]=v.y; T6[4]=v.z; T6[5]=v.w; }
            { float2 v = *(const float2*)&Sr[6][s + 8]; T6[6]=v.x; T6[7]=v.y; }
            T7[0] = Sr[7][s + 3];
            { float4 v = *(const float4*)&Sr[7][s + 4]; T7[1]=v.x; T7[2]=v.y; T7[3]=v.z; T7[4]=v.w; }
            T7[5] = Sr[7][s + 8];

            float4 res0, res1;
            float* r0p = (float*)&res0;
            float* r1p = (float*)&res1;
#pragma unroll
            for (int p = 0; p < 4; p++) {
                float d[16];
                // ---- center row y0 (roles R0..R6 = T0..T6) ----
                {
                    float ctr = T3[p + 4];
                    d[0]  = T3[p + 1] - ctr;   d[1]  = T4[p + 1] - ctr;
                    d[2]  = T5[p + 2] - ctr;   d[3]  = T6[p + 1] - ctr;
                    d[4]  = T6[p + 2] - ctr;   d[5]  = T6[p + 3] - ctr;
                    d[6]  = T5[p + 6] - ctr;   d[7]  = T4[p + 7] - ctr;
                    d[8]  = T3[p + 7] - ctr;   d[9]  = T2[p + 7] - ctr;
                    d[10] = T1[p + 4] - ctr;   d[11] = T0[p + 2] - ctr;
                    d[12] = T0[p + 1] - ctr;   d[13] = T0[p + 0] - ctr;
                    d[14] = T1[p + 0] - ctr;   d[15] = T2[p + 1] - ctr;
                    r0p[p] = detect16(d);
                }
                // ---- center row y0+1 (roles R0..R6 = T1..T7) ----
                {
                    float ctr = T4[p + 4];
                    d[0]  = T4[p + 1] - ctr;   d[1]  = T5[p + 1] - ctr;
                    d[2]  = T6[p + 0] - ctr;   d[3]  = T7[p + 0] - ctr;
                    d[4]  = T7[p + 1] - ctr;   d[5]  = T7[p + 2] - ctr;
                    d[6]  = T6[p + 4] - ctr;   d[7]  = T5[p + 7] - ctr;
                    d[8]  = T4[p + 7] - ctr;   d[9]  = T3[p + 7] - ctr;
                    d[10] = T2[p + 6] - ctr;   d[11] = T1[p + 3] - ctr;
                    d[12] = T1[p + 2] - ctr;   d[13] = T1[p + 1] - ctr;
                    d[14] = T2[p + 2] - ctr;   d[15] = T3[p + 1] - ctr;
                    r1p[p] = detect16(d);
                }
            }
            float* op0 = out + ((size_t)n * IMG_H + y0) * IMG_W + X0 + lane * 4;
            *(float4*)op0 = res0;
            *(float4*)(op0 + IMG_W) = res1;
        }
        par ^= 1;
    }
}

extern "C" void kernel_launch(void* const* d_in, const int* in_sizes, int n_in,
                              void* d_out, int out_size)
{
    const float* img = (const float*)d_in[0];
    float* out = (float*)d_out;
    int N = in_sizes[0] / (IMG_H * IMG_W);
    int total_tiles = TPI * N;     // 32400 for N=4

    dim3 block(96, 1, 1);
    dim3 grid(NB, 1, 1);
    fast_score_kernel<<<grid, block>>>(img, out, total_tiles);
}